// round 1
// baseline (speedup 1.0000x reference)
#include <cuda_runtime.h>
#include <math.h>

#define SQ   4096
#define NH   8
#define HD   128
#define EMB  1024
#define NT   32
#define TPK  8
#define NEGV (-1e10f)

// ---------------- scratch (static device globals; no allocs allowed) --------
__device__ float g_q[NH * SQ * HD];
__device__ float g_k[NH * SQ * HD];
__device__ float g_v[NH * SQ * HD];
__device__ float g_attn[SQ * EMB];
__device__ float g_tile[NH * NT * NT];
__device__ float g_repm[NH * NT];
__device__ float g_repl[NH * NT];

// ---------------- GEMM: C = A(MxK) @ B(KxN) fp32, 64x64 tile ----------------
// mode 0: C[m*N+n]   mode 1: scatter to [h][s][d] layout (n = h*128+d, m = s)
__global__ void gemm_kernel(const float* __restrict__ A,
                            const float* __restrict__ Bw,
                            float* __restrict__ C,
                            int M, int N, int K, int mode) {
    __shared__ float As[16][64];
    __shared__ float Bs[16][64];
    int tid = threadIdx.x;
    int tx = tid & 15, ty = tid >> 4;
    int bm = blockIdx.y * 64, bn = blockIdx.x * 64;
    float acc[4][4] = {};
    for (int k0 = 0; k0 < K; k0 += 16) {
        for (int idx = tid; idx < 1024; idx += 256) {
            int m = idx >> 4, c = idx & 15;
            As[c][m] = A[(size_t)(bm + m) * K + k0 + c];
        }
        for (int idx = tid; idx < 1024; idx += 256) {
            int n = idx & 63, c = idx >> 6;
            Bs[c][n] = Bw[(size_t)(k0 + c) * N + bn + n];
        }
        __syncthreads();
        #pragma unroll
        for (int kk = 0; kk < 16; kk++) {
            float af[4], bf[4];
            #pragma unroll
            for (int i = 0; i < 4; i++) af[i] = As[kk][4 * ty + i];
            #pragma unroll
            for (int j = 0; j < 4; j++) bf[j] = Bs[kk][4 * tx + j];
            #pragma unroll
            for (int i = 0; i < 4; i++)
                #pragma unroll
                for (int j = 0; j < 4; j++)
                    acc[i][j] = fmaf(af[i], bf[j], acc[i][j]);
        }
        __syncthreads();
    }
    #pragma unroll
    for (int i = 0; i < 4; i++) {
        int gm = bm + 4 * ty + i;
        #pragma unroll
        for (int j = 0; j < 4; j++) {
            int gn = bn + 4 * tx + j;
            if (mode == 0) {
                C[(size_t)gm * N + gn] = acc[i][j];
            } else {
                int h = gn >> 7, d = gn & 127;
                C[((size_t)h * M + gm) * 128 + d] = acc[i][j];
            }
        }
    }
}

// ---------------- RoPE (in place on g_q / g_k); q gets 1/sqrt(D) folded -----
__global__ void rope_kernel(const float* __restrict__ cosb,
                            const float* __restrict__ sinb) {
    int idx = blockIdx.x * blockDim.x + threadIdx.x;   // NH*SQ*64
    if (idx >= NH * SQ * 64) return;
    int d = idx & 63;
    int s = (idx >> 6) & (SQ - 1);
    int h = idx >> 18;
    float c = cosb[s * 64 + d], sn = sinb[s * 64 + d];
    const float qsc = 0.08838834764831845f; // 1/sqrt(128)
    float* q = g_q + ((size_t)h * SQ + s) * 128;
    float a = q[d], b = q[d + 64];
    q[d]      = (a * c - b * sn) * qsc;
    q[d + 64] = (b * c + a * sn) * qsc;
    float* k = g_k + ((size_t)h * SQ + s) * 128;
    a = k[d]; b = k[d + 64];
    k[d]      = a * c - b * sn;
    k[d + 64] = b * c + a * sn;
}

// ---------------- Flash attention, BQ=BK=64, fused anchor-tile stats --------
#define QPITCH 129
#define VPITCH 132
#define PPITCH 65
#define SMEM_FLOATS (64*QPITCH + 64*QPITCH + 64*VPITCH + 64*PPITCH + 1024 + 64*3 + 32)

__global__ void attn_kernel() {
    extern __shared__ float sm[];
    float* Qs     = sm;
    float* Ks     = Qs + 64 * QPITCH;
    float* Vs     = Ks + 64 * QPITCH;
    float* Ps     = Vs + 64 * VPITCH;
    float* red    = Ps + 64 * PPITCH;
    float* m_s    = red + 1024;
    float* l_s    = m_s + 64;
    float* al_s   = l_s + 64;
    float* tmax_s = al_s + 64;

    int qb = blockIdx.x, h = blockIdx.y;
    int tid = threadIdx.x, tx = tid & 15, ty = tid >> 4;

    const float* qptr = g_q + ((size_t)h * SQ + qb * 64) * 128;
    for (int idx = tid; idx < 8192; idx += 256) {
        int r = idx >> 7, d = idx & 127;
        Qs[r * QPITCH + d] = qptr[idx];
    }
    if (tid < 64) { m_s[tid] = -1e30f; l_s[tid] = 0.0f; }
    if (tid < 32) tmax_s[tid] = -1e30f;

    float o[4][8] = {};

    for (int kb = 0; kb <= qb; kb++) {
        __syncthreads();   // prior iter PV done / init visible
        const float* kptr = g_k + ((size_t)h * SQ + kb * 64) * 128;
        for (int idx = tid; idx < 8192; idx += 256) {
            int r = idx >> 7, d = idx & 127;
            Ks[r * QPITCH + d] = kptr[idx];
        }
        __syncthreads();

        float acc[4][4] = {};
        #pragma unroll 8
        for (int d = 0; d < 128; d++) {
            float qf[4], kf[4];
            #pragma unroll
            for (int i = 0; i < 4; i++) qf[i] = Qs[(4 * ty + i) * QPITCH + d];
            #pragma unroll
            for (int j = 0; j < 4; j++) kf[j] = Ks[(4 * tx + j) * QPITCH + d];
            #pragma unroll
            for (int i = 0; i < 4; i++)
                #pragma unroll
                for (int j = 0; j < 4; j++)
                    acc[i][j] = fmaf(qf[i], kf[j], acc[i][j]);
        }
        if (kb == qb) {
            #pragma unroll
            for (int i = 0; i < 4; i++)
                #pragma unroll
                for (int j = 0; j < 4; j++)
                    if (4 * tx + j > 4 * ty + i) acc[i][j] = NEGV;
        }
        // per-thread row maxes
        #pragma unroll
        for (int i = 0; i < 4; i++) {
            float tm = fmaxf(fmaxf(acc[i][0], acc[i][1]), fmaxf(acc[i][2], acc[i][3]));
            red[(4 * ty + i) * 16 + tx] = tm;
        }
        __syncthreads();
        if (tx == 0) {
            #pragma unroll
            for (int i = 0; i < 4; i++) {
                int r = 4 * ty + i;
                float mb = red[r * 16];
                #pragma unroll
                for (int t = 1; t < 16; t++) mb = fmaxf(mb, red[r * 16 + t]);
                if ((qb & 1) && r == 63)
                    tmax_s[kb >> 1] = fmaxf(tmax_s[kb >> 1], mb);
                float mo = m_s[r];
                float mn = fmaxf(mo, mb);
                al_s[r] = __expf(mo - mn);
                m_s[r] = mn;
            }
        }
        __syncthreads();
        // exp, write P, partial row sums, rescale O
        #pragma unroll
        for (int i = 0; i < 4; i++) {
            int r = 4 * ty + i;
            float mr = m_s[r];
            float ssum = 0.0f;
            #pragma unroll
            for (int j = 0; j < 4; j++) {
                float p = __expf(acc[i][j] - mr);
                Ps[r * PPITCH + 4 * tx + j] = p;
                ssum += p;
            }
            red[r * 16 + tx] = ssum;
            float a = al_s[r];
            #pragma unroll
            for (int c = 0; c < 8; c++) o[i][c] *= a;
        }
        // load V while P settles
        const float* vptr = g_v + ((size_t)h * SQ + kb * 64) * 128;
        for (int idx = tid; idx < 8192; idx += 256) {
            int r = idx >> 7, d = idx & 127;
            Vs[r * VPITCH + d] = vptr[idx];
        }
        __syncthreads();
        if (tx == 0) {
            #pragma unroll
            for (int i = 0; i < 4; i++) {
                int r = 4 * ty + i;
                float sres = 0.0f;
                #pragma unroll
                for (int t = 0; t < 16; t++) sres += red[r * 16 + t];
                l_s[r] = l_s[r] * al_s[r] + sres;
            }
        }
        // O += P @ V
        #pragma unroll 2
        for (int kk = 0; kk < 64; kk++) {
            float pf[4];
            #pragma unroll
            for (int i = 0; i < 4; i++) pf[i] = Ps[(4 * ty + i) * PPITCH + kk];
            float4 v0 = *(const float4*)&Vs[kk * VPITCH + 8 * tx];
            float4 v1 = *(const float4*)&Vs[kk * VPITCH + 8 * tx + 4];
            #pragma unroll
            for (int i = 0; i < 4; i++) {
                o[i][0] = fmaf(pf[i], v0.x, o[i][0]);
                o[i][1] = fmaf(pf[i], v0.y, o[i][1]);
                o[i][2] = fmaf(pf[i], v0.z, o[i][2]);
                o[i][3] = fmaf(pf[i], v0.w, o[i][3]);
                o[i][4] = fmaf(pf[i], v1.x, o[i][4]);
                o[i][5] = fmaf(pf[i], v1.y, o[i][5]);
                o[i][6] = fmaf(pf[i], v1.z, o[i][6]);
                o[i][7] = fmaf(pf[i], v1.w, o[i][7]);
            }
        }
    }
    __syncthreads();
    // epilogue: normalize, scatter to [s][h*128+d]
    #pragma unroll
    for (int i = 0; i < 4; i++) {
        int r = 4 * ty + i;
        float inv = 1.0f / l_s[r];
        float* dst = g_attn + (size_t)(qb * 64 + r) * EMB + h * 128 + 8 * tx;
        #pragma unroll
        for (int c = 0; c < 8; c++) dst[c] = o[i][c] * inv;
    }
    if (qb & 1) {
        int qt = qb >> 1;
        if (tid < 32) g_tile[((size_t)h * NT + qt) * NT + tid] = tmax_s[tid];
        if (tid == 0) {
            g_repm[h * NT + qt] = m_s[63];
            g_repl[h * NT + qt] = l_s[63];
        }
    }
}

// ---------------- anchor tile scores + top-8 (jax top_k tie semantics) ------
__global__ void topk_kernel(float* __restrict__ out) {
    int t = blockIdx.x * blockDim.x + threadIdx.x;
    if (t >= NH * NT) return;
    int qt = t & (NT - 1);
    float m = g_repm[t], l = g_repl[t];
    float sc[NT];
    #pragma unroll
    for (int kt = 0; kt < NT; kt++)
        sc[kt] = (kt <= qt) ? expf(g_tile[(size_t)t * NT + kt] - m) / l : 0.0f;
    float* dst = out + (size_t)SQ * EMB + (size_t)t * TPK;
    for (int r = 0; r < TPK; r++) {
        float bv = -1e38f; int bi = 0;
        #pragma unroll
        for (int kt = 0; kt < NT; kt++)
            if (sc[kt] > bv) { bv = sc[kt]; bi = kt; }
        sc[bi] = -1e38f;
        dst[r] = (float)bi;
    }
}

// ---------------- launch --------------------------------------------------
extern "C" void kernel_launch(void* const* d_in, const int* in_sizes, int n_in,
                              void* d_out, int out_size) {
    const float* x    = (const float*)d_in[0];
    const float* wq   = (const float*)d_in[1];
    const float* wk   = (const float*)d_in[2];
    const float* wv   = (const float*)d_in[3];
    const float* wo   = (const float*)d_in[4];
    const float* cosb = (const float*)d_in[5];
    const float* sinb = (const float*)d_in[6];
    float* out = (float*)d_out;

    void *pq = nullptr, *pk = nullptr, *pv = nullptr, *pattn = nullptr;
    cudaGetSymbolAddress(&pq, g_q);
    cudaGetSymbolAddress(&pk, g_k);
    cudaGetSymbolAddress(&pv, g_v);
    cudaGetSymbolAddress(&pattn, g_attn);

    dim3 gg(EMB / 64, SQ / 64);
    gemm_kernel<<<gg, 256>>>(x, wq, (float*)pq, SQ, EMB, EMB, 1);
    gemm_kernel<<<gg, 256>>>(x, wk, (float*)pk, SQ, EMB, EMB, 1);
    gemm_kernel<<<gg, 256>>>(x, wv, (float*)pv, SQ, EMB, EMB, 1);

    int rope_n = NH * SQ * 64;
    rope_kernel<<<(rope_n + 255) / 256, 256>>>(cosb, sinb);

    size_t smem_bytes = (size_t)SMEM_FLOATS * sizeof(float);
    cudaFuncSetAttribute(attn_kernel,
                         cudaFuncAttributeMaxDynamicSharedMemorySize,
                         (int)smem_bytes);
    attn_kernel<<<dim3(SQ / 64, NH), 256, smem_bytes>>>();

    gemm_kernel<<<gg, 256>>>((const float*)pattn, wo, out, SQ, EMB, EMB, 0);

    if (out_size >= SQ * EMB + NH * NT * TPK)
        topk_kernel<<<1, 256>>>(out);
}

// round 3
// speedup vs baseline: 1.7574x; 1.7574x over previous
#include <cuda_runtime.h>
#include <cuda_bf16.h>
#include <stdint.h>
#include <math.h>

#define SQ   4096
#define NH   8
#define HD   128
#define EMB  1024
#define NT   32
#define TPK  8
#define NEGV (-1e10f)

// ---------------- scratch (static device globals; no allocs allowed) --------
__device__ float g_q[NH * SQ * HD];
__device__ float g_k[NH * SQ * HD];
__device__ float g_v[NH * SQ * HD];
__device__ float g_tile[NH * NT * NT];
__device__ float g_repm[NH * NT];
__device__ float g_repl[NH * NT];
// bf16 split operands
__device__ __nv_bfloat16 g_xh[SQ * EMB];
__device__ __nv_bfloat16 g_xl[SQ * EMB];
__device__ __nv_bfloat16 g_wth[4 * EMB * EMB];   // [w][n][k] transposed
__device__ __nv_bfloat16 g_wtl[4 * EMB * EMB];
__device__ __nv_bfloat16 g_ah[SQ * EMB];
__device__ __nv_bfloat16 g_al[SQ * EMB];

// ======================= helpers ===========================================
__device__ __forceinline__ uint32_t smem_u32(const void* p) {
    uint32_t a;
    asm("{ .reg .u64 t; cvta.to.shared.u64 t, %1; cvt.u32.u64 %0, t; }"
        : "=r"(a) : "l"(p));
    return a;
}
#define SWZ(o) ((o) ^ (((o) >> 3) & 0x70))

__device__ __forceinline__ void ldmx4(uint32_t* r, uint32_t addr) {
    asm volatile("ldmatrix.sync.aligned.m8n8.x4.shared.b16 {%0,%1,%2,%3}, [%4];"
        : "=r"(r[0]), "=r"(r[1]), "=r"(r[2]), "=r"(r[3]) : "r"(addr));
}
__device__ __forceinline__ void mma16816(float* c, const uint32_t* a,
                                         const uint32_t* b) {
    asm volatile(
        "mma.sync.aligned.m16n8k16.row.col.f32.bf16.bf16.f32 "
        "{%0,%1,%2,%3}, {%4,%5,%6,%7}, {%8,%9}, {%0,%1,%2,%3};"
        : "+f"(c[0]), "+f"(c[1]), "+f"(c[2]), "+f"(c[3])
        : "r"(a[0]), "r"(a[1]), "r"(a[2]), "r"(a[3]), "r"(b[0]), "r"(b[1]));
}

// ======================= prep kernels =======================================
__global__ void split_kernel(const float* __restrict__ in,
                             __nv_bfloat16* __restrict__ hi,
                             __nv_bfloat16* __restrict__ lo, int n) {
    int i = blockIdx.x * blockDim.x + threadIdx.x;
    if (i >= n) return;
    float x = in[i];
    __nv_bfloat16 h = __float2bfloat16(x);
    hi[i] = h;
    lo[i] = __float2bfloat16(x - __bfloat162float(h));
}

// transpose + split 4 weights: W[k][n] fp32 -> Wt[n][k] bf16 hi/lo
__global__ void wprep_kernel(const float* __restrict__ w0, const float* __restrict__ w1,
                             const float* __restrict__ w2, const float* __restrict__ w3,
                             __nv_bfloat16* __restrict__ hi, __nv_bfloat16* __restrict__ lo) {
    __shared__ float t[32][33];
    const float* w = (blockIdx.z == 0) ? w0 : (blockIdx.z == 1) ? w1
                    : (blockIdx.z == 2) ? w2 : w3;
    int k0 = blockIdx.x * 32, n0 = blockIdx.y * 32;
    int tx = threadIdx.x, ty = threadIdx.y;     // 32 x 8
    for (int r = ty; r < 32; r += 8)
        t[r][tx] = w[(size_t)(k0 + r) * EMB + n0 + tx];
    __syncthreads();
    size_t base = (size_t)blockIdx.z * EMB * EMB;
    for (int r = ty; r < 32; r += 8) {
        float x = t[tx][r];                      // element [k0+tx][n0+r]
        __nv_bfloat16 h = __float2bfloat16(x);
        size_t o = base + (size_t)(n0 + r) * EMB + k0 + tx;
        hi[o] = h;
        lo[o] = __float2bfloat16(x - __bfloat162float(h));
    }
}

// ======================= HMMA GEMM ==========================================
// C[M,N] = A[M,K] @ W[K,N] via split: AhBh + AhBl + AlBh. B pre-transposed [n][k].
// block tile 128x128, BK=64, 8 warps (warp tile 32x64), mma.sync m16n8k16 bf16.
#define G_SMEM 65536

__global__ __launch_bounds__(256, 2) void gemm_tc(
    const __nv_bfloat16* __restrict__ Ah, const __nv_bfloat16* __restrict__ Al,
    const __nv_bfloat16* __restrict__ Bh, const __nv_bfloat16* __restrict__ Bl,
    float* __restrict__ C, int mode) {
    extern __shared__ __align__(1024) char smem[];
    char* pAH = smem;
    char* pAL = pAH + 16384;
    char* pBH = pAL + 16384;
    char* pBL = pBH + 16384;
    uint32_t saH = smem_u32(pAH), saL = smem_u32(pAL);
    uint32_t sbH = smem_u32(pBH), sbL = smem_u32(pBL);

    int tid = threadIdx.x, wid = tid >> 5, lid = tid & 31;
    int wm = wid & 3, wn = wid >> 2;          // warp tile: rows wm*32, cols wn*64
    int bm = blockIdx.y * 128, bn = blockIdx.x * 128;

    float acc[2][8][4];
    #pragma unroll
    for (int i = 0; i < 2; i++)
        #pragma unroll
        for (int j = 0; j < 8; j++)
            #pragma unroll
            for (int kq = 0; kq < 4; kq++) acc[i][j][kq] = 0.0f;

    uint32_t a_row0 = (uint32_t)(wm * 32 + (lid & 15));
    uint32_t a_kb   = (uint32_t)((lid >> 4) * 16);
    uint32_t b_row  = (uint32_t)(wn * 64 + ((lid >> 4) << 3) + (lid & 7));
    uint32_t b_half = (uint32_t)(((lid >> 3) & 1) * 16);

    for (int c = 0; c < 16; c++) {
        // fill 4 tiles: 128 rows x 64 bf16 (128B/row swizzled)
        #pragma unroll
        for (int t = tid; t < 1024; t += 256) {
            int r = t >> 3, kq = t & 7;
            uint32_t so = SWZ((uint32_t)(r * 128 + kq * 16));
            size_t ga = (size_t)(bm + r) * EMB + c * 64 + kq * 8;
            size_t gb = (size_t)(bn + r) * EMB + c * 64 + kq * 8;
            *(uint4*)(pAH + so) = *(const uint4*)(Ah + ga);
            *(uint4*)(pAL + so) = *(const uint4*)(Al + ga);
            *(uint4*)(pBH + so) = *(const uint4*)(Bh + gb);
            *(uint4*)(pBL + so) = *(const uint4*)(Bl + gb);
        }
        __syncthreads();
        #pragma unroll
        for (int ks = 0; ks < 4; ks++) {
            uint32_t kofs = (uint32_t)(ks * 32);
            uint32_t aH[2][4], aL[2][4];
            uint32_t o0 = SWZ(a_row0 * 128 + kofs + a_kb);
            uint32_t o1 = SWZ((a_row0 + 16) * 128 + kofs + a_kb);
            ldmx4(aH[0], saH + o0);
            ldmx4(aH[1], saH + o1);
            ldmx4(aL[0], saL + o0);
            ldmx4(aL[1], saL + o1);
            #pragma unroll
            for (int pg = 0; pg < 4; pg++) {
                uint32_t bo = SWZ((b_row + pg * 16) * 128 + kofs + b_half);
                uint32_t bH[4], bL[4];
                ldmx4(bH, sbH + bo);
                ldmx4(bL, sbL + bo);
                #pragma unroll
                for (int mt = 0; mt < 2; mt++)
                    #pragma unroll
                    for (int nt = 0; nt < 2; nt++) {
                        float* cc = acc[mt][pg * 2 + nt];
                        mma16816(cc, aH[mt], bH + nt * 2);
                        mma16816(cc, aH[mt], bL + nt * 2);
                        mma16816(cc, aL[mt], bH + nt * 2);
                    }
            }
        }
        __syncthreads();
    }

    // epilogue: write acc fragments straight to gmem
    int gr = lid >> 2, gc = (lid & 3) * 2;
    #pragma unroll
    for (int mt = 0; mt < 2; mt++) {
        int row0 = bm + wm * 32 + mt * 16 + gr;
        #pragma unroll
        for (int nt = 0; nt < 8; nt++) {
            int col = wn * 64 + nt * 8 + gc;
            float2 lo2 = make_float2(acc[mt][nt][0], acc[mt][nt][1]);
            float2 hi2 = make_float2(acc[mt][nt][2], acc[mt][nt][3]);
            if (mode == 0) {
                *(float2*)&C[(size_t)row0 * EMB + bn + col] = lo2;
                *(float2*)&C[(size_t)(row0 + 8) * EMB + bn + col] = hi2;
            } else {
                float* base = C + ((size_t)(bn >> 7) * SQ) * 128;
                *(float2*)&base[(size_t)row0 * 128 + col] = lo2;
                *(float2*)&base[(size_t)(row0 + 8) * 128 + col] = hi2;
            }
        }
    }
}

// ---------------- RoPE (in place on g_q / g_k); q gets 1/sqrt(D) folded -----
__global__ void rope_kernel(const float* __restrict__ cosb,
                            const float* __restrict__ sinb) {
    int idx = blockIdx.x * blockDim.x + threadIdx.x;   // NH*SQ*64
    if (idx >= NH * SQ * 64) return;
    int d = idx & 63;
    int s = (idx >> 6) & (SQ - 1);
    int h = idx >> 18;
    float c = cosb[s * 64 + d], sn = sinb[s * 64 + d];
    const float qsc = 0.08838834764831845f; // 1/sqrt(128)
    float* q = g_q + ((size_t)h * SQ + s) * 128;
    float a = q[d], b = q[d + 64];
    q[d]      = (a * c - b * sn) * qsc;
    q[d + 64] = (b * c + a * sn) * qsc;
    float* k = g_k + ((size_t)h * SQ + s) * 128;
    a = k[d]; b = k[d + 64];
    k[d]      = a * c - b * sn;
    k[d + 64] = b * c + a * sn;
}

// ---------------- Flash attention, BQ=BK=64, fused anchor-tile stats --------
#define QT 68
#define VPITCH 132
#define PPITCH 65
#define ATT_FLOATS (128*QT + 128*QT + 64*VPITCH + 64*PPITCH + 1024 + 64*3 + 32)

__global__ void attn_kernel(__nv_bfloat16* __restrict__ ah,
                            __nv_bfloat16* __restrict__ al) {
    extern __shared__ float sm[];
    float* Qs     = sm;                 // [d=128][r=64] pitch QT
    float* Ks     = Qs + 128 * QT;
    float* Vs     = Ks + 128 * QT;      // [kk=64][d=128] pitch VPITCH
    float* Ps     = Vs + 64 * VPITCH;   // [r=64][kk=64] pitch PPITCH
    float* red    = Ps + 64 * PPITCH;
    float* m_s    = red + 1024;
    float* l_s    = m_s + 64;
    float* al_s   = l_s + 64;
    float* tmax_s = al_s + 64;

    int qb = (gridDim.x - 1) - blockIdx.x;   // heavy blocks first
    int h = blockIdx.y;
    int tid = threadIdx.x, tx = tid & 15, ty = tid >> 4;

    const float* qptr = g_q + ((size_t)h * SQ + qb * 64) * 128;
    for (int idx = tid; idx < 8192; idx += 256) {
        int r = idx >> 7, d = idx & 127;
        Qs[d * QT + r] = qptr[idx];
    }
    if (tid < 64) { m_s[tid] = -1e30f; l_s[tid] = 0.0f; }
    if (tid < 32) tmax_s[tid] = -1e30f;

    float o[4][8] = {};

    for (int kb = 0; kb <= qb; kb++) {
        __syncthreads();
        const float* kptr = g_k + ((size_t)h * SQ + kb * 64) * 128;
        for (int idx = tid; idx < 8192; idx += 256) {
            int r = idx >> 7, d = idx & 127;
            Ks[d * QT + r] = kptr[idx];
        }
        __syncthreads();

        float acc[4][4] = {};
        #pragma unroll 4
        for (int d = 0; d < 128; d++) {
            float4 qv = *(const float4*)&Qs[d * QT + 4 * ty];
            float4 kv = *(const float4*)&Ks[d * QT + 4 * tx];
            float qf[4] = {qv.x, qv.y, qv.z, qv.w};
            float kf[4] = {kv.x, kv.y, kv.z, kv.w};
            #pragma unroll
            for (int i = 0; i < 4; i++)
                #pragma unroll
                for (int j = 0; j < 4; j++)
                    acc[i][j] = fmaf(qf[i], kf[j], acc[i][j]);
        }
        if (kb == qb) {
            #pragma unroll
            for (int i = 0; i < 4; i++)
                #pragma unroll
                for (int j = 0; j < 4; j++)
                    if (4 * tx + j > 4 * ty + i) acc[i][j] = NEGV;
        }
        #pragma unroll
        for (int i = 0; i < 4; i++) {
            float tm = fmaxf(fmaxf(acc[i][0], acc[i][1]), fmaxf(acc[i][2], acc[i][3]));
            red[(4 * ty + i) * 16 + tx] = tm;
        }
        __syncthreads();
        if (tx == 0) {
            #pragma unroll
            for (int i = 0; i < 4; i++) {
                int r = 4 * ty + i;
                float mb = red[r * 16];
                #pragma unroll
                for (int t = 1; t < 16; t++) mb = fmaxf(mb, red[r * 16 + t]);
                if ((qb & 1) && r == 63)
                    tmax_s[kb >> 1] = fmaxf(tmax_s[kb >> 1], mb);
                float mo = m_s[r];
                float mn = fmaxf(mo, mb);
                al_s[r] = __expf(mo - mn);
                m_s[r] = mn;
            }
        }
        __syncthreads();
        #pragma unroll
        for (int i = 0; i < 4; i++) {
            int r = 4 * ty + i;
            float mr = m_s[r];
            float ssum = 0.0f;
            #pragma unroll
            for (int j = 0; j < 4; j++) {
                float p = __expf(acc[i][j] - mr);
                Ps[r * PPITCH + 4 * tx + j] = p;
                ssum += p;
            }
            red[r * 16 + tx] = ssum;
            float a = al_s[r];
            #pragma unroll
            for (int c = 0; c < 8; c++) o[i][c] *= a;
        }
        const float* vptr = g_v + ((size_t)h * SQ + kb * 64) * 128;
        for (int idx = tid; idx < 8192; idx += 256) {
            int r = idx >> 7, d = idx & 127;
            Vs[r * VPITCH + d] = vptr[idx];
        }
        __syncthreads();
        if (tx == 0) {
            #pragma unroll
            for (int i = 0; i < 4; i++) {
                int r = 4 * ty + i;
                float sres = 0.0f;
                #pragma unroll
                for (int t = 0; t < 16; t++) sres += red[r * 16 + t];
                l_s[r] = l_s[r] * al_s[r] + sres;
            }
        }
        #pragma unroll 2
        for (int kk = 0; kk < 64; kk++) {
            float pf[4];
            #pragma unroll
            for (int i = 0; i < 4; i++) pf[i] = Ps[(4 * ty + i) * PPITCH + kk];
            float4 v0 = *(const float4*)&Vs[kk * VPITCH + 8 * tx];
            float4 v1 = *(const float4*)&Vs[kk * VPITCH + 8 * tx + 4];
            #pragma unroll
            for (int i = 0; i < 4; i++) {
                o[i][0] = fmaf(pf[i], v0.x, o[i][0]);
                o[i][1] = fmaf(pf[i], v0.y, o[i][1]);
                o[i][2] = fmaf(pf[i], v0.z, o[i][2]);
                o[i][3] = fmaf(pf[i], v0.w, o[i][3]);
                o[i][4] = fmaf(pf[i], v1.x, o[i][4]);
                o[i][5] = fmaf(pf[i], v1.y, o[i][5]);
                o[i][6] = fmaf(pf[i], v1.z, o[i][6]);
                o[i][7] = fmaf(pf[i], v1.w, o[i][7]);
            }
        }
    }
    __syncthreads();
    #pragma unroll
    for (int i = 0; i < 4; i++) {
        int r = 4 * ty + i;
        float inv = 1.0f / l_s[r];
        size_t base = (size_t)(qb * 64 + r) * EMB + h * 128 + 8 * tx;
        #pragma unroll
        for (int c = 0; c < 8; c++) {
            float val = o[i][c] * inv;
            __nv_bfloat16 hb = __float2bfloat16(val);
            ah[base + c] = hb;
            al[base + c] = __float2bfloat16(val - __bfloat162float(hb));
        }
    }
    if (qb & 1) {
        int qt = qb >> 1;
        if (tid < 32) g_tile[((size_t)h * NT + qt) * NT + tid] = tmax_s[tid];
        if (tid == 0) {
            g_repm[h * NT + qt] = m_s[63];
            g_repl[h * NT + qt] = l_s[63];
        }
    }
}

// ---------------- anchor tile scores + top-8 (jax top_k tie semantics) ------
__global__ void topk_kernel(float* __restrict__ out) {
    int t = blockIdx.x * blockDim.x + threadIdx.x;
    if (t >= NH * NT) return;
    int qt = t & (NT - 1);
    float m = g_repm[t], l = g_repl[t];
    float sc[NT];
    #pragma unroll
    for (int kt = 0; kt < NT; kt++)
        sc[kt] = (kt <= qt) ? expf(g_tile[(size_t)t * NT + kt] - m) / l : 0.0f;
    float* dst = out + (size_t)SQ * EMB + (size_t)t * TPK;
    for (int r = 0; r < TPK; r++) {
        float bv = -1e38f; int bi = 0;
        #pragma unroll
        for (int kt = 0; kt < NT; kt++)
            if (sc[kt] > bv) { bv = sc[kt]; bi = kt; }
        sc[bi] = -1e38f;
        dst[r] = (float)bi;
    }
}

// ---------------- launch ----------------------------------------------------
extern "C" void kernel_launch(void* const* d_in, const int* in_sizes, int n_in,
                              void* d_out, int out_size) {
    const float* x    = (const float*)d_in[0];
    const float* wq   = (const float*)d_in[1];
    const float* wk   = (const float*)d_in[2];
    const float* wv   = (const float*)d_in[3];
    const float* wo   = (const float*)d_in[4];
    const float* cosb = (const float*)d_in[5];
    const float* sinb = (const float*)d_in[6];
    float* out = (float*)d_out;

    void *pq, *pk, *pv, *pxh, *pxl, *pwth, *pwtl, *pah, *pal;
    cudaGetSymbolAddress(&pq, g_q);
    cudaGetSymbolAddress(&pk, g_k);
    cudaGetSymbolAddress(&pv, g_v);
    cudaGetSymbolAddress(&pxh, g_xh);
    cudaGetSymbolAddress(&pxl, g_xl);
    cudaGetSymbolAddress(&pwth, g_wth);
    cudaGetSymbolAddress(&pwtl, g_wtl);
    cudaGetSymbolAddress(&pah, g_ah);
    cudaGetSymbolAddress(&pal, g_al);
    __nv_bfloat16* xh = (__nv_bfloat16*)pxh;
    __nv_bfloat16* xl = (__nv_bfloat16*)pxl;
    __nv_bfloat16* wth = (__nv_bfloat16*)pwth;
    __nv_bfloat16* wtl = (__nv_bfloat16*)pwtl;
    __nv_bfloat16* ah = (__nv_bfloat16*)pah;
    __nv_bfloat16* al = (__nv_bfloat16*)pal;

    cudaFuncSetAttribute(gemm_tc, cudaFuncAttributeMaxDynamicSharedMemorySize, G_SMEM);
    size_t att_smem = (size_t)ATT_FLOATS * sizeof(float);
    cudaFuncSetAttribute(attn_kernel, cudaFuncAttributeMaxDynamicSharedMemorySize,
                         (int)att_smem);

    const size_t WSZ = (size_t)EMB * EMB;

    split_kernel<<<(SQ * EMB + 255) / 256, 256>>>(x, xh, xl, SQ * EMB);
    wprep_kernel<<<dim3(32, 32, 4), dim3(32, 8)>>>(wq, wk, wv, wo, wth, wtl);

    dim3 gg(EMB / 128, SQ / 128);
    gemm_tc<<<gg, 256, G_SMEM>>>(xh, xl, wth + 0 * WSZ, wtl + 0 * WSZ, (float*)pq, 1);
    gemm_tc<<<gg, 256, G_SMEM>>>(xh, xl, wth + 1 * WSZ, wtl + 1 * WSZ, (float*)pk, 1);
    gemm_tc<<<gg, 256, G_SMEM>>>(xh, xl, wth + 2 * WSZ, wtl + 2 * WSZ, (float*)pv, 1);

    int rope_n = NH * SQ * 64;
    rope_kernel<<<(rope_n + 255) / 256, 256>>>(cosb, sinb);

    attn_kernel<<<dim3(SQ / 64, NH), 256, att_smem>>>(ah, al);

    gemm_tc<<<gg, 256, G_SMEM>>>(ah, al, wth + 3 * WSZ, wtl + 3 * WSZ, out, 0);

    if (out_size >= SQ * EMB + NH * NT * TPK)
        topk_kernel<<<1, 256>>>(out);
}

// round 4
// speedup vs baseline: 4.4897x; 2.5547x over previous
#include <cuda_runtime.h>
#include <cuda_bf16.h>
#include <stdint.h>
#include <math.h>

#define SQ   4096
#define NH   8
#define HD   128
#define EMB  1024
#define NT   32
#define TPK  8
#define NEGV (-1e10f)

// ---------------- scratch (static device globals; no allocs allowed) --------
__device__ float g_q[NH * SQ * HD];
__device__ float g_k[NH * SQ * HD];
__device__ float g_tile[NH * NT * NT];
__device__ float g_repm[NH * NT];
__device__ float g_repl[NH * NT];
// bf16 split operands
__device__ __nv_bfloat16 g_xh[SQ * EMB];
__device__ __nv_bfloat16 g_xl[SQ * EMB];
__device__ __nv_bfloat16 g_wth[4 * EMB * EMB];   // [w][n][k] transposed
__device__ __nv_bfloat16 g_wtl[4 * EMB * EMB];
__device__ __nv_bfloat16 g_ah[SQ * EMB];
__device__ __nv_bfloat16 g_al[SQ * EMB];
// rope'd / split q,k and split v, head-major [h][s][d]
__device__ __nv_bfloat16 g_qh[NH * SQ * HD];
__device__ __nv_bfloat16 g_ql[NH * SQ * HD];
__device__ __nv_bfloat16 g_kh[NH * SQ * HD];
__device__ __nv_bfloat16 g_kl[NH * SQ * HD];
__device__ __nv_bfloat16 g_vh[NH * SQ * HD];
__device__ __nv_bfloat16 g_vl[NH * SQ * HD];

// ======================= helpers ===========================================
__device__ __forceinline__ uint32_t smem_u32(const void* p) {
    uint32_t a;
    asm("{ .reg .u64 t; cvta.to.shared.u64 t, %1; cvt.u32.u64 %0, t; }"
        : "=r"(a) : "l"(p));
    return a;
}
#define SWZ(o) ((o) ^ (((o) >> 3) & 0x70))      // 128B rows
#define SWZ256(o) ((o) ^ (((o) >> 4) & 0x70))   // 256B rows

__device__ __forceinline__ void ldmx4(uint32_t* r, uint32_t addr) {
    asm volatile("ldmatrix.sync.aligned.m8n8.x4.shared.b16 {%0,%1,%2,%3}, [%4];"
        : "=r"(r[0]), "=r"(r[1]), "=r"(r[2]), "=r"(r[3]) : "r"(addr));
}
__device__ __forceinline__ void ldmx4t(uint32_t* r, uint32_t addr) {
    asm volatile("ldmatrix.sync.aligned.m8n8.x4.trans.shared.b16 {%0,%1,%2,%3}, [%4];"
        : "=r"(r[0]), "=r"(r[1]), "=r"(r[2]), "=r"(r[3]) : "r"(addr));
}
__device__ __forceinline__ void mma16816(float* c, const uint32_t* a,
                                         const uint32_t* b) {
    asm volatile(
        "mma.sync.aligned.m16n8k16.row.col.f32.bf16.bf16.f32 "
        "{%0,%1,%2,%3}, {%4,%5,%6,%7}, {%8,%9}, {%0,%1,%2,%3};"
        : "+f"(c[0]), "+f"(c[1]), "+f"(c[2]), "+f"(c[3])
        : "r"(a[0]), "r"(a[1]), "r"(a[2]), "r"(a[3]), "r"(b[0]), "r"(b[1]));
}
__device__ __forceinline__ uint32_t bpack(float lo, float hi) {
    __nv_bfloat162 v;
    v.x = __float2bfloat16(lo);
    v.y = __float2bfloat16(hi);
    return *reinterpret_cast<uint32_t*>(&v);
}

// ======================= prep kernels =======================================
__global__ void split_kernel(const float* __restrict__ in,
                             __nv_bfloat16* __restrict__ hi,
                             __nv_bfloat16* __restrict__ lo, int n) {
    int i = blockIdx.x * blockDim.x + threadIdx.x;
    if (i >= n) return;
    float x = in[i];
    __nv_bfloat16 h = __float2bfloat16(x);
    hi[i] = h;
    lo[i] = __float2bfloat16(x - __bfloat162float(h));
}

// transpose + split 4 weights: W[k][n] fp32 -> Wt[n][k] bf16 hi/lo
__global__ void wprep_kernel(const float* __restrict__ w0, const float* __restrict__ w1,
                             const float* __restrict__ w2, const float* __restrict__ w3,
                             __nv_bfloat16* __restrict__ hi, __nv_bfloat16* __restrict__ lo) {
    __shared__ float t[32][33];
    const float* w = (blockIdx.z == 0) ? w0 : (blockIdx.z == 1) ? w1
                    : (blockIdx.z == 2) ? w2 : w3;
    int k0 = blockIdx.x * 32, n0 = blockIdx.y * 32;
    int tx = threadIdx.x, ty = threadIdx.y;     // 32 x 8
    for (int r = ty; r < 32; r += 8)
        t[r][tx] = w[(size_t)(k0 + r) * EMB + n0 + tx];
    __syncthreads();
    size_t base = (size_t)blockIdx.z * EMB * EMB;
    for (int r = ty; r < 32; r += 8) {
        float x = t[tx][r];
        __nv_bfloat16 h = __float2bfloat16(x);
        size_t o = base + (size_t)(n0 + r) * EMB + k0 + tx;
        hi[o] = h;
        lo[o] = __float2bfloat16(x - __bfloat162float(h));
    }
}

// ======================= HMMA GEMM ==========================================
// C = A @ W, 3-term bf16 split. B pre-transposed [n][k].
// mode 0: fp32 row-major [m][EMB]; mode 1: fp32 head-major;
// mode 2: bf16 split head-major (Ch/Cl).
#define G_SMEM 65536

__global__ __launch_bounds__(256, 2) void gemm_tc(
    const __nv_bfloat16* __restrict__ Ah, const __nv_bfloat16* __restrict__ Al,
    const __nv_bfloat16* __restrict__ Bh, const __nv_bfloat16* __restrict__ Bl,
    float* __restrict__ C, __nv_bfloat16* __restrict__ Ch,
    __nv_bfloat16* __restrict__ Cl, int mode) {
    extern __shared__ __align__(1024) char smem[];
    char* pAH = smem;
    char* pAL = pAH + 16384;
    char* pBH = pAL + 16384;
    char* pBL = pBH + 16384;
    uint32_t saH = smem_u32(pAH), saL = smem_u32(pAL);
    uint32_t sbH = smem_u32(pBH), sbL = smem_u32(pBL);

    int tid = threadIdx.x, wid = tid >> 5, lid = tid & 31;
    int wm = wid & 3, wn = wid >> 2;
    int bm = blockIdx.y * 128, bn = blockIdx.x * 128;

    float acc[2][8][4];
    #pragma unroll
    for (int i = 0; i < 2; i++)
        #pragma unroll
        for (int j = 0; j < 8; j++)
            #pragma unroll
            for (int kq = 0; kq < 4; kq++) acc[i][j][kq] = 0.0f;

    uint32_t a_row0 = (uint32_t)(wm * 32 + (lid & 15));
    uint32_t a_kb   = (uint32_t)((lid >> 4) * 16);
    uint32_t b_row  = (uint32_t)(wn * 64 + ((lid >> 4) << 3) + (lid & 7));
    uint32_t b_half = (uint32_t)(((lid >> 3) & 1) * 16);

    for (int c = 0; c < 16; c++) {
        #pragma unroll
        for (int t = tid; t < 1024; t += 256) {
            int r = t >> 3, kq = t & 7;
            uint32_t so = SWZ((uint32_t)(r * 128 + kq * 16));
            size_t ga = (size_t)(bm + r) * EMB + c * 64 + kq * 8;
            size_t gb = (size_t)(bn + r) * EMB + c * 64 + kq * 8;
            *(uint4*)(pAH + so) = *(const uint4*)(Ah + ga);
            *(uint4*)(pAL + so) = *(const uint4*)(Al + ga);
            *(uint4*)(pBH + so) = *(const uint4*)(Bh + gb);
            *(uint4*)(pBL + so) = *(const uint4*)(Bl + gb);
        }
        __syncthreads();
        #pragma unroll
        for (int ks = 0; ks < 4; ks++) {
            uint32_t kofs = (uint32_t)(ks * 32);
            uint32_t aH[2][4], aL[2][4];
            uint32_t o0 = SWZ(a_row0 * 128 + kofs + a_kb);
            uint32_t o1 = SWZ((a_row0 + 16) * 128 + kofs + a_kb);
            ldmx4(aH[0], saH + o0);
            ldmx4(aH[1], saH + o1);
            ldmx4(aL[0], saL + o0);
            ldmx4(aL[1], saL + o1);
            #pragma unroll
            for (int pg = 0; pg < 4; pg++) {
                uint32_t bo = SWZ((b_row + pg * 16) * 128 + kofs + b_half);
                uint32_t bH[4], bL[4];
                ldmx4(bH, sbH + bo);
                ldmx4(bL, sbL + bo);
                #pragma unroll
                for (int mt = 0; mt < 2; mt++)
                    #pragma unroll
                    for (int nt = 0; nt < 2; nt++) {
                        float* cc = acc[mt][pg * 2 + nt];
                        mma16816(cc, aH[mt], bH + nt * 2);
                        mma16816(cc, aH[mt], bL + nt * 2);
                        mma16816(cc, aL[mt], bH + nt * 2);
                    }
            }
        }
        __syncthreads();
    }

    int gr = lid >> 2, gc = (lid & 3) * 2;
    #pragma unroll
    for (int mt = 0; mt < 2; mt++) {
        int row0 = bm + wm * 32 + mt * 16 + gr;
        #pragma unroll
        for (int nt = 0; nt < 8; nt++) {
            int col = wn * 64 + nt * 8 + gc;
            float v0 = acc[mt][nt][0], v1 = acc[mt][nt][1];
            float v2 = acc[mt][nt][2], v3 = acc[mt][nt][3];
            if (mode == 0) {
                *(float2*)&C[(size_t)row0 * EMB + bn + col] = make_float2(v0, v1);
                *(float2*)&C[(size_t)(row0 + 8) * EMB + bn + col] = make_float2(v2, v3);
            } else if (mode == 1) {
                float* base = C + ((size_t)(bn >> 7) * SQ) * 128;
                *(float2*)&base[(size_t)row0 * 128 + col] = make_float2(v0, v1);
                *(float2*)&base[(size_t)(row0 + 8) * 128 + col] = make_float2(v2, v3);
            } else {
                size_t hb = ((size_t)(bn >> 7) * SQ) * 128;
                __nv_bfloat16 h0 = __float2bfloat16(v0);
                __nv_bfloat16 h1 = __float2bfloat16(v1);
                __nv_bfloat16 h2 = __float2bfloat16(v2);
                __nv_bfloat16 h3 = __float2bfloat16(v3);
                *(uint32_t*)&Ch[hb + (size_t)row0 * 128 + col] =
                    bpack(v0, v1) * 0 + (((uint32_t)*(uint16_t*)&h1) << 16 | *(uint16_t*)&h0);
                *(uint32_t*)&Ch[hb + (size_t)(row0 + 8) * 128 + col] =
                    (((uint32_t)*(uint16_t*)&h3) << 16 | *(uint16_t*)&h2);
                *(uint32_t*)&Cl[hb + (size_t)row0 * 128 + col] =
                    bpack(v0 - __bfloat162float(h0), v1 - __bfloat162float(h1));
                *(uint32_t*)&Cl[hb + (size_t)(row0 + 8) * 128 + col] =
                    bpack(v2 - __bfloat162float(h2), v3 - __bfloat162float(h3));
            }
        }
    }
}

// ---------------- RoPE: fp32 q/k -> rotated bf16 hi/lo splits ---------------
__global__ void rope_kernel(const float* __restrict__ cosb,
                            const float* __restrict__ sinb) {
    int idx = blockIdx.x * blockDim.x + threadIdx.x;   // NH*SQ*64
    if (idx >= NH * SQ * 64) return;
    int d = idx & 63;
    int s = (idx >> 6) & (SQ - 1);
    int h = idx >> 18;
    float c = cosb[s * 64 + d], sn = sinb[s * 64 + d];
    const float qsc = 0.08838834764831845f; // 1/sqrt(128)
    size_t base = ((size_t)h * SQ + s) * 128;
    float a = g_q[base + d], b = g_q[base + d + 64];
    float q0 = (a * c - b * sn) * qsc;
    float q1 = (b * c + a * sn) * qsc;
    __nv_bfloat16 t;
    t = __float2bfloat16(q0); g_qh[base + d] = t;
    g_ql[base + d] = __float2bfloat16(q0 - __bfloat162float(t));
    t = __float2bfloat16(q1); g_qh[base + d + 64] = t;
    g_ql[base + d + 64] = __float2bfloat16(q1 - __bfloat162float(t));
    a = g_k[base + d]; b = g_k[base + d + 64];
    float k0 = a * c - b * sn;
    float k1 = b * c + a * sn;
    t = __float2bfloat16(k0); g_kh[base + d] = t;
    g_kl[base + d] = __float2bfloat16(k0 - __bfloat162float(t));
    t = __float2bfloat16(k1); g_kh[base + d + 64] = t;
    g_kl[base + d + 64] = __float2bfloat16(k1 - __bfloat162float(t));
}

// ============ tensor-core flash attention, BQ=128, BK=64 ====================
#define ATT_SMEM (131072 + 128)

__global__ __launch_bounds__(256, 1) void attn_tc(
    __nv_bfloat16* __restrict__ ah, __nv_bfloat16* __restrict__ al) {
    extern __shared__ __align__(1024) char sm[];
    char* sQh = sm;                 // 32KB, [128 r][128 d] bf16, 256B rows
    char* sQl = sm + 32768;
    char* sKh = sm + 65536;         // 16KB, [64 k][128 d]
    char* sKl = sm + 81920;
    char* sVh = sm + 98304;
    char* sVl = sm + 114688;
    float* tmax_s = (float*)(sm + 131072);
    uint32_t uQh = smem_u32(sQh), uQl = smem_u32(sQl);
    uint32_t uKh = smem_u32(sKh), uKl = smem_u32(sKl);
    uint32_t uVh = smem_u32(sVh), uVl = smem_u32(sVl);

    int qb = (NT - 1) - blockIdx.x;   // heavy tiles first
    int h = blockIdx.y;
    int tid = threadIdx.x, wid = tid >> 5, lid = tid & 31;
    int gr = lid >> 2, qc = lid & 3;

    // load Q hi/lo (128x128 bf16 each)
    {
        const __nv_bfloat16* qh = g_qh + ((size_t)h * SQ + qb * 128) * 128;
        const __nv_bfloat16* ql = g_ql + ((size_t)h * SQ + qb * 128) * 128;
        for (int i = tid; i < 2048; i += 256) {
            int r = i >> 4, ch = i & 15;
            uint32_t so = SWZ256((uint32_t)(r * 256 + ch * 16));
            *(uint4*)(sQh + so) = *(const uint4*)(qh + r * 128 + ch * 8);
            *(uint4*)(sQl + so) = *(const uint4*)(ql + r * 128 + ch * 8);
        }
    }
    if (tid < 32) tmax_s[tid] = -1e30f;

    float o[16][4];
    #pragma unroll
    for (int j = 0; j < 16; j++)
        #pragma unroll
        for (int i = 0; i < 4; i++) o[j][i] = 0.0f;
    float m0 = -1e30f, m1 = -1e30f, l0 = 0.0f, l1 = 0.0f;

    int row0 = qb * 128 + wid * 16 + gr;
    int row1 = row0 + 8;

    // fragment address components
    uint32_t qa_row = (uint32_t)(wid * 16 + (lid & 15));
    uint32_t qa_kb  = (uint32_t)((lid >> 4) * 16);
    uint32_t kb_row = (uint32_t)(((lid >> 4) << 3) + (lid & 7));
    uint32_t kb_hf  = (uint32_t)(((lid >> 3) & 1) * 16);
    uint32_t v_row  = (uint32_t)(((lid >> 3) & 1) * 8 + (lid & 7));
    uint32_t v_col  = (uint32_t)((lid >> 4) << 4);   // bytes

    int nkb = 2 * qb + 2;
    for (int kb = 0; kb < nkb; kb++) {
        __syncthreads();
        {   // load K/V hi/lo (64x128 each)
            size_t gb = ((size_t)h * SQ + kb * 64) * 128;
            for (int i = tid; i < 1024; i += 256) {
                int r = i >> 4, ch = i & 15;
                uint32_t so = SWZ256((uint32_t)(r * 256 + ch * 16));
                size_t go = gb + r * 128 + ch * 8;
                *(uint4*)(sKh + so) = *(const uint4*)(g_kh + go);
                *(uint4*)(sKl + so) = *(const uint4*)(g_kl + go);
                *(uint4*)(sVh + so) = *(const uint4*)(g_vh + go);
                *(uint4*)(sVl + so) = *(const uint4*)(g_vl + go);
            }
        }
        __syncthreads();

        // ---- S = Q K^T (3-term split) ----
        float s[8][4];
        #pragma unroll
        for (int j = 0; j < 8; j++)
            #pragma unroll
            for (int i = 0; i < 4; i++) s[j][i] = 0.0f;

        #pragma unroll
        for (int dc = 0; dc < 8; dc++) {
            uint32_t qo = SWZ256(qa_row * 256 + (uint32_t)(dc * 32) + qa_kb);
            uint32_t aH[4], aL[4];
            ldmx4(aH, uQh + qo);
            ldmx4(aL, uQl + qo);
            #pragma unroll
            for (int nf = 0; nf < 4; nf++) {
                uint32_t ko = SWZ256((kb_row + nf * 16) * 256 + (uint32_t)(dc * 32) + kb_hf);
                uint32_t bH[4], bL[4];
                ldmx4(bH, uKh + ko);
                ldmx4(bL, uKl + ko);
                #pragma unroll
                for (int nt = 0; nt < 2; nt++) {
                    float* cc = s[nf * 2 + nt];
                    mma16816(cc, aH, bH + nt * 2);
                    mma16816(cc, aH, bL + nt * 2);
                    mma16816(cc, aL, bH + nt * 2);
                }
            }
        }
        // ---- causal mask (only the last two kb per tile can cross) ----
        if (kb >= 2 * qb) {
            #pragma unroll
            for (int j = 0; j < 8; j++) {
                int colb = kb * 64 + j * 8 + 2 * qc;
                if (colb > row0)     s[j][0] = NEGV;
                if (colb + 1 > row0) s[j][1] = NEGV;
                if (colb > row1)     s[j][2] = NEGV;
                if (colb + 1 > row1) s[j][3] = NEGV;
            }
        }
        // ---- row max ----
        float tm0 = -1e30f, tm1 = -1e30f;
        #pragma unroll
        for (int j = 0; j < 8; j++) {
            tm0 = fmaxf(tm0, fmaxf(s[j][0], s[j][1]));
            tm1 = fmaxf(tm1, fmaxf(s[j][2], s[j][3]));
        }
        tm0 = fmaxf(tm0, __shfl_xor_sync(0xffffffffu, tm0, 1));
        tm0 = fmaxf(tm0, __shfl_xor_sync(0xffffffffu, tm0, 2));
        tm1 = fmaxf(tm1, __shfl_xor_sync(0xffffffffu, tm1, 1));
        tm1 = fmaxf(tm1, __shfl_xor_sync(0xffffffffu, tm1, 2));
        // rep row (127) per-half-tile max
        if (wid == 7 && lid == 28)
            tmax_s[kb >> 1] = fmaxf(tmax_s[kb >> 1], tm1);
        // ---- online softmax state ----
        float mn0 = fmaxf(m0, tm0), mn1 = fmaxf(m1, tm1);
        float al0 = __expf(m0 - mn0), al1 = __expf(m1 - mn1);
        m0 = mn0; m1 = mn1;
        #pragma unroll
        for (int j = 0; j < 16; j++) {
            o[j][0] *= al0; o[j][1] *= al0;
            o[j][2] *= al1; o[j][3] *= al1;
        }
        float rs0 = 0.0f, rs1 = 0.0f;
        // ---- P (exp + split) fed straight into PV mma ----
        #pragma unroll
        for (int t = 0; t < 4; t++) {
            uint32_t pH[4], pL[4];
            #pragma unroll
            for (int jj = 0; jj < 2; jj++) {
                int j = 2 * t + jj;
                float e0 = __expf(s[j][0] - m0);
                float e1 = __expf(s[j][1] - m0);
                float e2 = __expf(s[j][2] - m1);
                float e3 = __expf(s[j][3] - m1);
                rs0 += e0 + e1; rs1 += e2 + e3;
                __nv_bfloat16 b0 = __float2bfloat16(e0);
                __nv_bfloat16 b1 = __float2bfloat16(e1);
                __nv_bfloat16 b2 = __float2bfloat16(e2);
                __nv_bfloat16 b3 = __float2bfloat16(e3);
                __nv_bfloat162 ph0; ph0.x = b0; ph0.y = b1;
                __nv_bfloat162 ph1; ph1.x = b2; ph1.y = b3;
                pH[2 * jj]     = *(uint32_t*)&ph0;
                pH[2 * jj + 1] = *(uint32_t*)&ph1;
                pL[2 * jj]     = bpack(e0 - __bfloat162float(b0),
                                       e1 - __bfloat162float(b1));
                pL[2 * jj + 1] = bpack(e2 - __bfloat162float(b2),
                                       e3 - __bfloat162float(b3));
            }
            #pragma unroll
            for (int nf = 0; nf < 8; nf++) {
                uint32_t vo = SWZ256((uint32_t)((t * 16 + v_row) * 256 + nf * 32) + v_col);
                uint32_t vH[4], vL[4];
                ldmx4t(vH, uVh + vo);
                ldmx4t(vL, uVl + vo);
                #pragma unroll
                for (int nt = 0; nt < 2; nt++) {
                    float* cc = o[nf * 2 + nt];
                    mma16816(cc, pH, vH + nt * 2);
                    mma16816(cc, pH, vL + nt * 2);
                    mma16816(cc, pL, vH + nt * 2);
                }
            }
        }
        rs0 += __shfl_xor_sync(0xffffffffu, rs0, 1);
        rs0 += __shfl_xor_sync(0xffffffffu, rs0, 2);
        rs1 += __shfl_xor_sync(0xffffffffu, rs1, 1);
        rs1 += __shfl_xor_sync(0xffffffffu, rs1, 2);
        l0 = l0 * al0 + rs0;
        l1 = l1 * al1 + rs1;
    }

    // ---- epilogue: normalize, split to bf16 hi/lo, write [s][h*128+d] ----
    float inv0 = 1.0f / l0, inv1 = 1.0f / l1;
    #pragma unroll
    for (int j = 0; j < 16; j++) {
        int col = h * 128 + j * 8 + 2 * qc;
        float v0 = o[j][0] * inv0, v1 = o[j][1] * inv0;
        float v2 = o[j][2] * inv1, v3 = o[j][3] * inv1;
        __nv_bfloat16 b0 = __float2bfloat16(v0);
        __nv_bfloat16 b1 = __float2bfloat16(v1);
        __nv_bfloat16 b2 = __float2bfloat16(v2);
        __nv_bfloat16 b3 = __float2bfloat16(v3);
        __nv_bfloat162 p0; p0.x = b0; p0.y = b1;
        __nv_bfloat162 p1; p1.x = b2; p1.y = b3;
        *(uint32_t*)&ah[(size_t)row0 * EMB + col] = *(uint32_t*)&p0;
        *(uint32_t*)&ah[(size_t)row1 * EMB + col] = *(uint32_t*)&p1;
        *(uint32_t*)&al[(size_t)row0 * EMB + col] =
            bpack(v0 - __bfloat162float(b0), v1 - __bfloat162float(b1));
        *(uint32_t*)&al[(size_t)row1 * EMB + col] =
            bpack(v2 - __bfloat162float(b2), v3 - __bfloat162float(b3));
    }
    if (wid == 7 && lid == 28) {
        g_repm[h * NT + qb] = m1;
        g_repl[h * NT + qb] = l1;
    }
    __syncthreads();
    if (tid < 32)
        g_tile[((size_t)h * NT + qb) * NT + tid] = tmax_s[tid];
}

// ---------------- anchor tile scores + top-8 (jax top_k tie semantics) ------
__global__ void topk_kernel(float* __restrict__ out) {
    int t = blockIdx.x * blockDim.x + threadIdx.x;
    if (t >= NH * NT) return;
    int qt = t & (NT - 1);
    float m = g_repm[t], l = g_repl[t];
    float sc[NT];
    #pragma unroll
    for (int kt = 0; kt < NT; kt++)
        sc[kt] = (kt <= qt) ? expf(g_tile[(size_t)t * NT + kt] - m) / l : 0.0f;
    float* dst = out + (size_t)SQ * EMB + (size_t)t * TPK;
    for (int r = 0; r < TPK; r++) {
        float bv = -1e38f; int bi = 0;
        #pragma unroll
        for (int kt = 0; kt < NT; kt++)
            if (sc[kt] > bv) { bv = sc[kt]; bi = kt; }
        sc[bi] = -1e38f;
        dst[r] = (float)bi;
    }
}

// ---------------- launch ----------------------------------------------------
extern "C" void kernel_launch(void* const* d_in, const int* in_sizes, int n_in,
                              void* d_out, int out_size) {
    const float* x    = (const float*)d_in[0];
    const float* wq   = (const float*)d_in[1];
    const float* wk   = (const float*)d_in[2];
    const float* wv   = (const float*)d_in[3];
    const float* wo   = (const float*)d_in[4];
    const float* cosb = (const float*)d_in[5];
    const float* sinb = (const float*)d_in[6];
    float* out = (float*)d_out;

    void *pq, *pk, *pxh, *pxl, *pwth, *pwtl, *pah, *pal, *pvh, *pvl;
    cudaGetSymbolAddress(&pq, g_q);
    cudaGetSymbolAddress(&pk, g_k);
    cudaGetSymbolAddress(&pxh, g_xh);
    cudaGetSymbolAddress(&pxl, g_xl);
    cudaGetSymbolAddress(&pwth, g_wth);
    cudaGetSymbolAddress(&pwtl, g_wtl);
    cudaGetSymbolAddress(&pah, g_ah);
    cudaGetSymbolAddress(&pal, g_al);
    cudaGetSymbolAddress(&pvh, g_vh);
    cudaGetSymbolAddress(&pvl, g_vl);
    __nv_bfloat16* xh = (__nv_bfloat16*)pxh;
    __nv_bfloat16* xl = (__nv_bfloat16*)pxl;
    __nv_bfloat16* wth = (__nv_bfloat16*)pwth;
    __nv_bfloat16* wtl = (__nv_bfloat16*)pwtl;
    __nv_bfloat16* ah = (__nv_bfloat16*)pah;
    __nv_bfloat16* al = (__nv_bfloat16*)pal;

    cudaFuncSetAttribute(gemm_tc, cudaFuncAttributeMaxDynamicSharedMemorySize, G_SMEM);
    cudaFuncSetAttribute(attn_tc, cudaFuncAttributeMaxDynamicSharedMemorySize, ATT_SMEM);

    const size_t WSZ = (size_t)EMB * EMB;

    split_kernel<<<(SQ * EMB + 255) / 256, 256>>>(x, xh, xl, SQ * EMB);
    wprep_kernel<<<dim3(32, 32, 4), dim3(32, 8)>>>(wq, wk, wv, wo, wth, wtl);

    dim3 gg(EMB / 128, SQ / 128);
    gemm_tc<<<gg, 256, G_SMEM>>>(xh, xl, wth + 0 * WSZ, wtl + 0 * WSZ,
                                 (float*)pq, nullptr, nullptr, 1);
    gemm_tc<<<gg, 256, G_SMEM>>>(xh, xl, wth + 1 * WSZ, wtl + 1 * WSZ,
                                 (float*)pk, nullptr, nullptr, 1);
    gemm_tc<<<gg, 256, G_SMEM>>>(xh, xl, wth + 2 * WSZ, wtl + 2 * WSZ,
                                 nullptr, (__nv_bfloat16*)pvh, (__nv_bfloat16*)pvl, 2);

    int rope_n = NH * SQ * 64;
    rope_kernel<<<(rope_n + 255) / 256, 256>>>(cosb, sinb);

    attn_tc<<<dim3(NT, NH), 256, ATT_SMEM>>>(ah, al);

    gemm_tc<<<gg, 256, G_SMEM>>>(ah, al, wth + 3 * WSZ, wtl + 3 * WSZ,
                                 out, nullptr, nullptr, 0);

    if (out_size >= SQ * EMB + NH * NT * TPK)
        topk_kernel<<<1, 256>>>(out);
}

// round 6
// speedup vs baseline: 5.7062x; 1.2709x over previous
#include <cuda_runtime.h>
#include <cuda_bf16.h>
#include <stdint.h>
#include <math.h>

#define SQ   4096
#define NH   8
#define HD   128
#define EMB  1024
#define NT   32
#define TPK  8
#define NEGV (-1e10f)

// ---------------- scratch (static device globals; no allocs allowed) --------
__device__ float g_q[NH * SQ * HD];
__device__ float g_k[NH * SQ * HD];
__device__ float g_tile[NH * NT * NT];
__device__ float g_repm[NH * NT];
__device__ float g_repl[NH * NT];
__device__ __nv_bfloat16 g_xh[SQ * EMB];
__device__ __nv_bfloat16 g_xl[SQ * EMB];
__device__ __nv_bfloat16 g_wth[4 * EMB * EMB];   // [w][n][k] transposed
__device__ __nv_bfloat16 g_wtl[4 * EMB * EMB];
__device__ __nv_bfloat16 g_ah[SQ * EMB];
__device__ __nv_bfloat16 g_al[SQ * EMB];
__device__ __nv_bfloat16 g_qh[NH * SQ * HD];
__device__ __nv_bfloat16 g_ql[NH * SQ * HD];
__device__ __nv_bfloat16 g_kh[NH * SQ * HD];
__device__ __nv_bfloat16 g_kl[NH * SQ * HD];
__device__ __nv_bfloat16 g_vh[NH * SQ * HD];
__device__ __nv_bfloat16 g_vl[NH * SQ * HD];

// ======================= helpers ===========================================
__device__ __forceinline__ uint32_t smem_u32(const void* p) {
    uint32_t a;
    asm("{ .reg .u64 t; cvta.to.shared.u64 t, %1; cvt.u32.u64 %0, t; }"
        : "=r"(a) : "l"(p));
    return a;
}
#define SWZ64(o)  ((o) ^ (((o) >> 3) & 0x30))   // 64B rows
#define SWZ256(o) ((o) ^ (((o) >> 4) & 0x70))   // 256B rows

__device__ __forceinline__ void cp16(uint32_t dst, const void* src) {
    asm volatile("cp.async.cg.shared.global [%0], [%1], 16;"
                 :: "r"(dst), "l"(src));
}
__device__ __forceinline__ void cp_commit() {
    asm volatile("cp.async.commit_group;" ::: "memory");
}
__device__ __forceinline__ void cp_wait1() {
    asm volatile("cp.async.wait_group 1;" ::: "memory");
}
__device__ __forceinline__ void ldmx4(uint32_t* r, uint32_t addr) {
    asm volatile("ldmatrix.sync.aligned.m8n8.x4.shared.b16 {%0,%1,%2,%3}, [%4];"
        : "=r"(r[0]), "=r"(r[1]), "=r"(r[2]), "=r"(r[3]) : "r"(addr));
}
__device__ __forceinline__ void ldmx4t(uint32_t* r, uint32_t addr) {
    asm volatile("ldmatrix.sync.aligned.m8n8.x4.trans.shared.b16 {%0,%1,%2,%3}, [%4];"
        : "=r"(r[0]), "=r"(r[1]), "=r"(r[2]), "=r"(r[3]) : "r"(addr));
}
__device__ __forceinline__ void mma16816(float* c, const uint32_t* a,
                                         const uint32_t* b) {
    asm volatile(
        "mma.sync.aligned.m16n8k16.row.col.f32.bf16.bf16.f32 "
        "{%0,%1,%2,%3}, {%4,%5,%6,%7}, {%8,%9}, {%0,%1,%2,%3};"
        : "+f"(c[0]), "+f"(c[1]), "+f"(c[2]), "+f"(c[3])
        : "r"(a[0]), "r"(a[1]), "r"(a[2]), "r"(a[3]), "r"(b[0]), "r"(b[1]));
}
__device__ __forceinline__ uint32_t bpack(float lo, float hi) {
    __nv_bfloat162 v;
    v.x = __float2bfloat16(lo);
    v.y = __float2bfloat16(hi);
    return *reinterpret_cast<uint32_t*>(&v);
}

// ======================= prep kernels =======================================
__global__ void split_kernel(const float* __restrict__ in,
                             __nv_bfloat16* __restrict__ hi,
                             __nv_bfloat16* __restrict__ lo, int n) {
    int i = blockIdx.x * blockDim.x + threadIdx.x;
    if (i >= n) return;
    float x = in[i];
    __nv_bfloat16 h = __float2bfloat16(x);
    hi[i] = h;
    lo[i] = __float2bfloat16(x - __bfloat162float(h));
}

__global__ void wprep_kernel(const float* __restrict__ w0, const float* __restrict__ w1,
                             const float* __restrict__ w2, const float* __restrict__ w3,
                             __nv_bfloat16* __restrict__ hi, __nv_bfloat16* __restrict__ lo) {
    __shared__ float t[32][33];
    const float* w = (blockIdx.z == 0) ? w0 : (blockIdx.z == 1) ? w1
                    : (blockIdx.z == 2) ? w2 : w3;
    int k0 = blockIdx.x * 32, n0 = blockIdx.y * 32;
    int tx = threadIdx.x, ty = threadIdx.y;
    for (int r = ty; r < 32; r += 8)
        t[r][tx] = w[(size_t)(k0 + r) * EMB + n0 + tx];
    __syncthreads();
    size_t base = (size_t)blockIdx.z * EMB * EMB;
    for (int r = ty; r < 32; r += 8) {
        float x = t[tx][r];
        __nv_bfloat16 h = __float2bfloat16(x);
        size_t o = base + (size_t)(n0 + r) * EMB + k0 + tx;
        hi[o] = h;
        lo[o] = __float2bfloat16(x - __bfloat162float(h));
    }
}

// ======================= HMMA GEMM (2-stage cp.async, BK=32) ================
// modes: 0 = fp32 row-major out; 3 = combined QKV (z=0 q fp32 hm, z=1 k fp32 hm,
// z=2 v bf16 split hm)
#define G_STAGE 32768
#define G_SMEM  (2 * G_STAGE)

__global__ __launch_bounds__(256, 2) void gemm_tc(
    const __nv_bfloat16* __restrict__ Ah, const __nv_bfloat16* __restrict__ Al,
    const __nv_bfloat16* __restrict__ Bh, const __nv_bfloat16* __restrict__ Bl,
    float* __restrict__ C, int mode) {
    extern __shared__ __align__(1024) char smem[];
    uint32_t sb = smem_u32(smem);

    int tid = threadIdx.x, wid = tid >> 5, lid = tid & 31;
    int wm = wid & 3, wn = wid >> 2;
    int bm = blockIdx.y * 128, bn = blockIdx.x * 128;
    if (mode == 3) {
        size_t zofs = (size_t)blockIdx.z * EMB * EMB;
        Bh += zofs; Bl += zofs;
    }

    float acc[2][8][4];
    #pragma unroll
    for (int i = 0; i < 2; i++)
        #pragma unroll
        for (int j = 0; j < 8; j++)
            #pragma unroll
            for (int kq = 0; kq < 4; kq++) acc[i][j][kq] = 0.0f;

    uint32_t a_row0 = (uint32_t)(wm * 32 + (lid & 15));
    uint32_t a_kb   = (uint32_t)((lid >> 4) * 16);
    uint32_t b_row  = (uint32_t)(wn * 64 + ((lid >> 4) << 3) + (lid & 7));
    uint32_t b_half = (uint32_t)(((lid >> 3) & 1) * 16);

    // chunk loader: BK=32 -> 4 tiles x 128 rows x 64B; 8 cp16 per thread
    auto issue = [&](int c, int stg) {
        uint32_t base = sb + stg * G_STAGE;
        #pragma unroll
        for (int it = 0; it < 2; it++) {
            int i = tid + it * 256;             // 0..511 : (r,u) pairs
            int r = i >> 2, u = i & 3;
            uint32_t so = SWZ64((uint32_t)(r * 64 + u * 16));
            size_t ga = (size_t)(bm + r) * EMB + c * 32 + u * 8;
            size_t gb = (size_t)(bn + r) * EMB + c * 32 + u * 8;
            cp16(base + so,          Ah + ga);
            cp16(base + 8192 + so,   Al + ga);
            cp16(base + 16384 + so,  Bh + gb);
            cp16(base + 24576 + so,  Bl + gb);
        }
    };

    issue(0, 0); cp_commit();
    issue(1, 1); cp_commit();

    for (int c = 0; c < 32; c++) {
        int stg = c & 1;
        cp_wait1();
        __syncthreads();
        uint32_t saH = sb + stg * G_STAGE;
        uint32_t saL = saH + 8192;
        uint32_t sbH = saH + 16384;
        uint32_t sbL = saH + 24576;
        #pragma unroll
        for (int ks = 0; ks < 2; ks++) {
            uint32_t kofs = (uint32_t)(ks * 32);
            uint32_t aH[2][4], aL[2][4];
            uint32_t o0 = SWZ64(a_row0 * 64 + kofs + a_kb);
            uint32_t o1 = SWZ64((a_row0 + 16) * 64 + kofs + a_kb);
            ldmx4(aH[0], saH + o0);
            ldmx4(aH[1], saH + o1);
            ldmx4(aL[0], saL + o0);
            ldmx4(aL[1], saL + o1);
            #pragma unroll
            for (int pg = 0; pg < 4; pg++) {
                uint32_t bo = SWZ64((b_row + pg * 16) * 64 + kofs + b_half);
                uint32_t bH[4], bL[4];
                ldmx4(bH, sbH + bo);
                ldmx4(bL, sbL + bo);
                #pragma unroll
                for (int mt = 0; mt < 2; mt++)
                    #pragma unroll
                    for (int nt = 0; nt < 2; nt++) {
                        float* cc = acc[mt][pg * 2 + nt];
                        mma16816(cc, aH[mt], bH + nt * 2);
                        mma16816(cc, aH[mt], bL + nt * 2);
                        mma16816(cc, aL[mt], bH + nt * 2);
                    }
            }
        }
        __syncthreads();
        if (c + 2 < 32) issue(c + 2, stg);
        cp_commit();
    }

    int gr = lid >> 2, gc = (lid & 3) * 2;
    int z = (mode == 3) ? blockIdx.z : -1;
    #pragma unroll
    for (int mt = 0; mt < 2; mt++) {
        int row0 = bm + wm * 32 + mt * 16 + gr;
        #pragma unroll
        for (int nt = 0; nt < 8; nt++) {
            int col = wn * 64 + nt * 8 + gc;
            float v0 = acc[mt][nt][0], v1 = acc[mt][nt][1];
            float v2 = acc[mt][nt][2], v3 = acc[mt][nt][3];
            if (mode == 0) {
                *(float2*)&C[(size_t)row0 * EMB + bn + col] = make_float2(v0, v1);
                *(float2*)&C[(size_t)(row0 + 8) * EMB + bn + col] = make_float2(v2, v3);
            } else if (z == 0 || z == 1) {
                float* base = (z == 0 ? g_q : g_k) + ((size_t)(bn >> 7) * SQ) * 128;
                *(float2*)&base[(size_t)row0 * 128 + col] = make_float2(v0, v1);
                *(float2*)&base[(size_t)(row0 + 8) * 128 + col] = make_float2(v2, v3);
            } else {
                size_t hb = ((size_t)(bn >> 7) * SQ) * 128;
                __nv_bfloat16 h0 = __float2bfloat16(v0);
                __nv_bfloat16 h1 = __float2bfloat16(v1);
                __nv_bfloat16 h2 = __float2bfloat16(v2);
                __nv_bfloat16 h3 = __float2bfloat16(v3);
                *(uint32_t*)&g_vh[hb + (size_t)row0 * 128 + col] =
                    (((uint32_t)*(uint16_t*)&h1) << 16) | *(uint16_t*)&h0;
                *(uint32_t*)&g_vh[hb + (size_t)(row0 + 8) * 128 + col] =
                    (((uint32_t)*(uint16_t*)&h3) << 16) | *(uint16_t*)&h2;
                *(uint32_t*)&g_vl[hb + (size_t)row0 * 128 + col] =
                    bpack(v0 - __bfloat162float(h0), v1 - __bfloat162float(h1));
                *(uint32_t*)&g_vl[hb + (size_t)(row0 + 8) * 128 + col] =
                    bpack(v2 - __bfloat162float(h2), v3 - __bfloat162float(h3));
            }
        }
    }
}

// ---------------- RoPE: fp32 q/k -> rotated bf16 hi/lo splits ---------------
__global__ void rope_kernel(const float* __restrict__ cosb,
                            const float* __restrict__ sinb) {
    int idx = blockIdx.x * blockDim.x + threadIdx.x;
    if (idx >= NH * SQ * 64) return;
    int d = idx & 63;
    int s = (idx >> 6) & (SQ - 1);
    int h = idx >> 18;
    float c = cosb[s * 64 + d], sn = sinb[s * 64 + d];
    const float qsc = 0.08838834764831845f;
    size_t base = ((size_t)h * SQ + s) * 128;
    float a = g_q[base + d], b = g_q[base + d + 64];
    float q0 = (a * c - b * sn) * qsc;
    float q1 = (b * c + a * sn) * qsc;
    __nv_bfloat16 t;
    t = __float2bfloat16(q0); g_qh[base + d] = t;
    g_ql[base + d] = __float2bfloat16(q0 - __bfloat162float(t));
    t = __float2bfloat16(q1); g_qh[base + d + 64] = t;
    g_ql[base + d + 64] = __float2bfloat16(q1 - __bfloat162float(t));
    a = g_k[base + d]; b = g_k[base + d + 64];
    float k0 = a * c - b * sn;
    float k1 = b * c + a * sn;
    t = __float2bfloat16(k0); g_kh[base + d] = t;
    g_kl[base + d] = __float2bfloat16(k0 - __bfloat162float(t));
    t = __float2bfloat16(k1); g_kh[base + d + 64] = t;
    g_kl[base + d + 64] = __float2bfloat16(k1 - __bfloat162float(t));
}

// ============ tensor-core flash attention, BQ=128, BK=64, 2-stage KV ========
#define A_STAGE 65536
#define ATT_SMEM (65536 + 2 * A_STAGE + 128)

__global__ __launch_bounds__(256, 1) void attn_tc(
    __nv_bfloat16* __restrict__ ah, __nv_bfloat16* __restrict__ al) {
    extern __shared__ __align__(1024) char sm[];
    char* sQh = sm;                 // 32KB Qh + 32KB Ql, 256B rows
    char* sQl = sm + 32768;
    float* tmax_s = (float*)(sm + 65536 + 2 * A_STAGE);
    uint32_t uQh = smem_u32(sQh), uQl = smem_u32(sQl);
    uint32_t uKV = smem_u32(sm + 65536);   // stage base

    int qb = (NT - 1) - blockIdx.x;
    int h = blockIdx.y;
    int tid = threadIdx.x, wid = tid >> 5, lid = tid & 31;
    int gr = lid >> 2, qc = lid & 3;

    {
        const __nv_bfloat16* qh = g_qh + ((size_t)h * SQ + qb * 128) * 128;
        const __nv_bfloat16* ql = g_ql + ((size_t)h * SQ + qb * 128) * 128;
        for (int i = tid; i < 2048; i += 256) {
            int r = i >> 4, ch = i & 15;
            uint32_t so = SWZ256((uint32_t)(r * 256 + ch * 16));
            *(uint4*)(sQh + so) = *(const uint4*)(qh + r * 128 + ch * 8);
            *(uint4*)(sQl + so) = *(const uint4*)(ql + r * 128 + ch * 8);
        }
    }
    if (tid < 32) tmax_s[tid] = -1e30f;

    float o[16][4];
    #pragma unroll
    for (int j = 0; j < 16; j++)
        #pragma unroll
        for (int i = 0; i < 4; i++) o[j][i] = 0.0f;
    float m0 = -1e30f, m1 = -1e30f, l0 = 0.0f, l1 = 0.0f;

    int row0 = qb * 128 + wid * 16 + gr;
    int row1 = row0 + 8;

    uint32_t qa_row = (uint32_t)(wid * 16 + (lid & 15));
    uint32_t qa_kb  = (uint32_t)((lid >> 4) * 16);
    uint32_t kb_row = (uint32_t)(((lid >> 4) << 3) + (lid & 7));
    uint32_t kb_hf  = (uint32_t)(((lid >> 3) & 1) * 16);
    uint32_t v_row  = (uint32_t)(((lid >> 3) & 1) * 8 + (lid & 7));
    uint32_t v_col  = (uint32_t)((lid >> 4) << 4);

    int nkb = 2 * qb + 2;

    // KV chunk loader: 4 tiles x 64 rows x 16 units x 16B, 16 cp16/thread
    auto issue = [&](int kb, int stg) {
        uint32_t base = uKV + stg * A_STAGE;
        size_t gb = ((size_t)h * SQ + kb * 64) * 128;
        #pragma unroll
        for (int it = 0; it < 4; it++) {
            int i = tid + it * 256;            // 0..1023
            int r = i >> 4, u = i & 15;
            uint32_t so = SWZ256((uint32_t)(r * 256 + u * 16));
            size_t go = gb + r * 128 + u * 8;
            cp16(base + so,          g_kh + go);
            cp16(base + 16384 + so,  g_kl + go);
            cp16(base + 32768 + so,  g_vh + go);
            cp16(base + 49152 + so,  g_vl + go);
        }
    };

    issue(0, 0); cp_commit();
    issue(1, 1); cp_commit();

    for (int kb = 0; kb < nkb; kb++) {
        int stg = kb & 1;
        cp_wait1();
        __syncthreads();
        uint32_t uKh = uKV + stg * A_STAGE;
        uint32_t uKl = uKh + 16384;
        uint32_t uVh = uKh + 32768;
        uint32_t uVl = uKh + 49152;

        // ---- S = Q K^T ----
        float s[8][4];
        #pragma unroll
        for (int j = 0; j < 8; j++)
            #pragma unroll
            for (int i = 0; i < 4; i++) s[j][i] = 0.0f;

        #pragma unroll
        for (int dc = 0; dc < 8; dc++) {
            uint32_t qo = SWZ256(qa_row * 256 + (uint32_t)(dc * 32) + qa_kb);
            uint32_t aH[4], aL[4];
            ldmx4(aH, uQh + qo);
            ldmx4(aL, uQl + qo);
            #pragma unroll
            for (int nf = 0; nf < 4; nf++) {
                uint32_t ko = SWZ256((kb_row + nf * 16) * 256 + (uint32_t)(dc * 32) + kb_hf);
                uint32_t bH[4], bL[4];
                ldmx4(bH, uKh + ko);
                ldmx4(bL, uKl + ko);
                #pragma unroll
                for (int nt = 0; nt < 2; nt++) {
                    float* cc = s[nf * 2 + nt];
                    mma16816(cc, aH, bH + nt * 2);
                    mma16816(cc, aH, bL + nt * 2);
                    mma16816(cc, aL, bH + nt * 2);
                }
            }
        }
        if (kb >= 2 * qb) {
            #pragma unroll
            for (int j = 0; j < 8; j++) {
                int colb = kb * 64 + j * 8 + 2 * qc;
                if (colb > row0)     s[j][0] = NEGV;
                if (colb + 1 > row0) s[j][1] = NEGV;
                if (colb > row1)     s[j][2] = NEGV;
                if (colb + 1 > row1) s[j][3] = NEGV;
            }
        }
        float tm0 = -1e30f, tm1 = -1e30f;
        #pragma unroll
        for (int j = 0; j < 8; j++) {
            tm0 = fmaxf(tm0, fmaxf(s[j][0], s[j][1]));
            tm1 = fmaxf(tm1, fmaxf(s[j][2], s[j][3]));
        }
        tm0 = fmaxf(tm0, __shfl_xor_sync(0xffffffffu, tm0, 1));
        tm0 = fmaxf(tm0, __shfl_xor_sync(0xffffffffu, tm0, 2));
        tm1 = fmaxf(tm1, __shfl_xor_sync(0xffffffffu, tm1, 1));
        tm1 = fmaxf(tm1, __shfl_xor_sync(0xffffffffu, tm1, 2));
        if (wid == 7 && lid == 28)
            tmax_s[kb >> 1] = fmaxf(tmax_s[kb >> 1], tm1);
        float mn0 = fmaxf(m0, tm0), mn1 = fmaxf(m1, tm1);
        float al0 = __expf(m0 - mn0), al1 = __expf(m1 - mn1);
        m0 = mn0; m1 = mn1;
        #pragma unroll
        for (int j = 0; j < 16; j++) {
            o[j][0] *= al0; o[j][1] *= al0;
            o[j][2] *= al1; o[j][3] *= al1;
        }
        float rs0 = 0.0f, rs1 = 0.0f;
        #pragma unroll
        for (int t = 0; t < 4; t++) {
            uint32_t pH[4], pL[4];
            #pragma unroll
            for (int jj = 0; jj < 2; jj++) {
                int j = 2 * t + jj;
                float e0 = __expf(s[j][0] - m0);
                float e1 = __expf(s[j][1] - m0);
                float e2 = __expf(s[j][2] - m1);
                float e3 = __expf(s[j][3] - m1);
                rs0 += e0 + e1; rs1 += e2 + e3;
                __nv_bfloat16 b0 = __float2bfloat16(e0);
                __nv_bfloat16 b1 = __float2bfloat16(e1);
                __nv_bfloat16 b2 = __float2bfloat16(e2);
                __nv_bfloat16 b3 = __float2bfloat16(e3);
                __nv_bfloat162 ph0; ph0.x = b0; ph0.y = b1;
                __nv_bfloat162 ph1; ph1.x = b2; ph1.y = b3;
                pH[2 * jj]     = *(uint32_t*)&ph0;
                pH[2 * jj + 1] = *(uint32_t*)&ph1;
                pL[2 * jj]     = bpack(e0 - __bfloat162float(b0),
                                       e1 - __bfloat162float(b1));
                pL[2 * jj + 1] = bpack(e2 - __bfloat162float(b2),
                                       e3 - __bfloat162float(b3));
            }
            #pragma unroll
            for (int nf = 0; nf < 8; nf++) {
                uint32_t vo = SWZ256((uint32_t)((t * 16 + v_row) * 256 + nf * 32) + v_col);
                uint32_t vH[4], vL[4];
                ldmx4t(vH, uVh + vo);
                ldmx4t(vL, uVl + vo);
                #pragma unroll
                for (int nt = 0; nt < 2; nt++) {
                    float* cc = o[nf * 2 + nt];
                    mma16816(cc, pH, vH + nt * 2);
                    mma16816(cc, pH, vL + nt * 2);
                    mma16816(cc, pL, vH + nt * 2);
                }
            }
        }
        rs0 += __shfl_xor_sync(0xffffffffu, rs0, 1);
        rs0 += __shfl_xor_sync(0xffffffffu, rs0, 2);
        rs1 += __shfl_xor_sync(0xffffffffu, rs1, 1);
        rs1 += __shfl_xor_sync(0xffffffffu, rs1, 2);
        l0 = l0 * al0 + rs0;
        l1 = l1 * al1 + rs1;

        __syncthreads();
        if (kb + 2 < nkb) issue(kb + 2, stg);
        cp_commit();
    }

    float inv0 = 1.0f / l0, inv1 = 1.0f / l1;
    #pragma unroll
    for (int j = 0; j < 16; j++) {
        int col = h * 128 + j * 8 + 2 * qc;
        float v0 = o[j][0] * inv0, v1 = o[j][1] * inv0;
        float v2 = o[j][2] * inv1, v3 = o[j][3] * inv1;
        __nv_bfloat16 b0 = __float2bfloat16(v0);
        __nv_bfloat16 b1 = __float2bfloat16(v1);
        __nv_bfloat16 b2 = __float2bfloat16(v2);
        __nv_bfloat16 b3 = __float2bfloat16(v3);
        __nv_bfloat162 p0; p0.x = b0; p0.y = b1;
        __nv_bfloat162 p1; p1.x = b2; p1.y = b3;
        *(uint32_t*)&ah[(size_t)row0 * EMB + col] = *(uint32_t*)&p0;
        *(uint32_t*)&ah[(size_t)row1 * EMB + col] = *(uint32_t*)&p1;
        *(uint32_t*)&al[(size_t)row0 * EMB + col] =
            bpack(v0 - __bfloat162float(b0), v1 - __bfloat162float(b1));
        *(uint32_t*)&al[(size_t)row1 * EMB + col] =
            bpack(v2 - __bfloat162float(b2), v3 - __bfloat162float(b3));
    }
    if (wid == 7 && lid == 28) {
        g_repm[h * NT + qb] = m1;
        g_repl[h * NT + qb] = l1;
    }
    __syncthreads();
    if (tid < 32)
        g_tile[((size_t)h * NT + qb) * NT + tid] = tmax_s[tid];
}

// ---------------- anchor tile scores + top-8 --------------------------------
__global__ void topk_kernel(float* __restrict__ out) {
    int t = blockIdx.x * blockDim.x + threadIdx.x;
    if (t >= NH * NT) return;
    int qt = t & (NT - 1);
    float m = g_repm[t], l = g_repl[t];
    float sc[NT];
    #pragma unroll
    for (int kt = 0; kt < NT; kt++)
        sc[kt] = (kt <= qt) ? expf(g_tile[(size_t)t * NT + kt] - m) / l : 0.0f;
    float* dst = out + (size_t)SQ * EMB + (size_t)t * TPK;
    for (int r = 0; r < TPK; r++) {
        float bv = -1e38f; int bi = 0;
        #pragma unroll
        for (int kt = 0; kt < NT; kt++)
            if (sc[kt] > bv) { bv = sc[kt]; bi = kt; }
        sc[bi] = -1e38f;
        dst[r] = (float)bi;
    }
}

// ---------------- launch ----------------------------------------------------
extern "C" void kernel_launch(void* const* d_in, const int* in_sizes, int n_in,
                              void* d_out, int out_size) {
    const float* x    = (const float*)d_in[0];
    const float* wq   = (const float*)d_in[1];
    const float* wk   = (const float*)d_in[2];
    const float* wv   = (const float*)d_in[3];
    const float* wo   = (const float*)d_in[4];
    const float* cosb = (const float*)d_in[5];
    const float* sinb = (const float*)d_in[6];
    float* out = (float*)d_out;

    void *pxh, *pxl, *pwth, *pwtl, *pah, *pal;
    cudaGetSymbolAddress(&pxh, g_xh);
    cudaGetSymbolAddress(&pxl, g_xl);
    cudaGetSymbolAddress(&pwth, g_wth);
    cudaGetSymbolAddress(&pwtl, g_wtl);
    cudaGetSymbolAddress(&pah, g_ah);
    cudaGetSymbolAddress(&pal, g_al);
    __nv_bfloat16* xh = (__nv_bfloat16*)pxh;
    __nv_bfloat16* xl = (__nv_bfloat16*)pxl;
    __nv_bfloat16* wth = (__nv_bfloat16*)pwth;
    __nv_bfloat16* wtl = (__nv_bfloat16*)pwtl;
    __nv_bfloat16* ah = (__nv_bfloat16*)pah;
    __nv_bfloat16* al = (__nv_bfloat16*)pal;

    cudaFuncSetAttribute(gemm_tc, cudaFuncAttributeMaxDynamicSharedMemorySize, G_SMEM);
    cudaFuncSetAttribute(attn_tc, cudaFuncAttributeMaxDynamicSharedMemorySize, ATT_SMEM);

    const size_t WSZ = (size_t)EMB * EMB;

    split_kernel<<<(SQ * EMB + 255) / 256, 256>>>(x, xh, xl, SQ * EMB);
    wprep_kernel<<<dim3(32, 32, 4), dim3(32, 8)>>>(wq, wk, wv, wo, wth, wtl);

    // combined QKV (z = 0,1,2)
    gemm_tc<<<dim3(EMB / 128, SQ / 128, 3), 256, G_SMEM>>>(
        xh, xl, wth, wtl, nullptr, 3);

    int rope_n = NH * SQ * 64;
    rope_kernel<<<(rope_n + 255) / 256, 256>>>(cosb, sinb);

    attn_tc<<<dim3(NT, NH), 256, ATT_SMEM>>>(ah, al);

    gemm_tc<<<dim3(EMB / 128, SQ / 128), 256, G_SMEM>>>(
        ah, al, wth + 3 * WSZ, wtl + 3 * WSZ, out, 0);

    if (out_size >= SQ * EMB + NH * NT * TPK)
        topk_kernel<<<1, 256>>>(out);
}